// round 2
// baseline (speedup 1.0000x reference)
#include <cuda_runtime.h>

#define N_NODES 50000
#define N_EDGES 800000
#define IN_CH 128
#define HID 64

// ---------------- scratch (static device globals: allocation-free) ----------
__device__ float g_deg[N_NODES];
__device__ float g_agg[N_NODES * 64];
__device__ float g_y[N_NODES * 64];
__device__ float g_h[N_NODES * 64];

// ---------------- zero agg (+deg) -------------------------------------------
__global__ void zero_kernel(int zero_deg) {
    int i = blockIdx.x * blockDim.x + threadIdx.x;
    int stride = gridDim.x * blockDim.x;
    for (int j = i; j < N_NODES * 64; j += stride) g_agg[j] = 0.f;
    if (zero_deg) {
        for (int j = i; j < N_NODES; j += stride) g_deg[j] = 0.f;
    }
}

// ---------------- degree ----------------------------------------------------
__global__ void deg_kernel(const int* __restrict__ dst) {
    int e = blockIdx.x * blockDim.x + threadIdx.x;
    if (e < N_EDGES) atomicAdd(&g_deg[dst[e]], 1.0f);
}

// ---------------- edge scatter: agg[dst] += y[src], 64 floats per edge ------
// 16 threads per edge, each owns one float4; red.global.add.v4.f32 (sm_90+)
__global__ void scatter_kernel(const int* __restrict__ src,
                               const int* __restrict__ dst) {
    int idx = blockIdx.x * blockDim.x + threadIdx.x;
    int e = idx >> 4;
    if (e >= N_EDGES) return;
    int c = (idx & 15) << 2;
    int s = __ldg(src + e);
    int d = __ldg(dst + e);
    float4 v = *(const float4*)(g_y + (size_t)s * 64 + c);
    float* p = g_agg + (size_t)d * 64 + c;
    asm volatile("red.global.add.v4.f32 [%0], {%1, %2, %3, %4};"
                 :: "l"(p), "f"(v.x), "f"(v.y), "f"(v.z), "f"(v.w)
                 : "memory");
}

// ---------------- GEMM: C[N,64] = A[N,K] @ W[K,64] (+ optional epilogue) ----
// 256 threads, 64 rows/block, per-thread 4x4 register tile.
// Smem: Ws[64][64] (k-chunk x cols), As[64][68] (k-chunk x rows, padded
// pitch 68 floats = 272B: keeps 16B alignment for LDS.128 and kills the
// 16-way write conflict of the transpose store).
// ASEL: 0 = Aext param, 1 = g_h.  DSEL: 0 = g_y, 1 = g_h, 2 = Cext param.
template<int K, bool COMBINE, int ASEL, int DSEL>
__global__ void __launch_bounds__(256) gemm64(const float* __restrict__ Aext,
                                              const float* __restrict__ W,
                                              const float* __restrict__ bias,
                                              float* __restrict__ Cext) {
    const float* A = (ASEL == 1) ? (const float*)g_h : Aext;
    float* C = (DSEL == 0) ? (float*)g_y
             : (DSEL == 1) ? (float*)g_h : Cext;

    __shared__ float Ws[64][64];
    __shared__ float As[64][68];

    int tid = threadIdx.x;
    int tx = tid & 15;   // col group: cols tx*4..tx*4+3
    int ty = tid >> 4;   // row group: rows ty*4..ty*4+3
    int rbase = blockIdx.x * 64;

    float acc[4][4] = {};

    for (int kc = 0; kc < K; kc += 64) {
        // cooperative stage of W chunk [64k x 64c] and A chunk (transposed)
        #pragma unroll
        for (int i = 0; i < 4; i++) {
            int li = tid + i * 256;
            int k = li >> 4;
            int c4 = (li & 15) << 2;
            *(float4*)&Ws[k][c4] =
                *(const float4*)(W + (size_t)(kc + k) * 64 + c4);

            int r  = li >> 4;
            int k4 = (li & 15) << 2;
            int gr = rbase + r;
            float4 a = make_float4(0.f, 0.f, 0.f, 0.f);
            if (gr < N_NODES)
                a = *(const float4*)(A + (size_t)gr * K + kc + k4);
            As[k4 + 0][r] = a.x;
            As[k4 + 1][r] = a.y;
            As[k4 + 2][r] = a.z;
            As[k4 + 3][r] = a.w;
        }
        __syncthreads();

        #pragma unroll 8
        for (int k = 0; k < 64; k++) {
            float4 a = *(const float4*)&As[k][ty * 4];  // 4 rows (2 distinct/warp -> broadcast)
            float4 w = *(const float4*)&Ws[k][tx * 4];  // 4 cols
            acc[0][0] += a.x * w.x; acc[0][1] += a.x * w.y;
            acc[0][2] += a.x * w.z; acc[0][3] += a.x * w.w;
            acc[1][0] += a.y * w.x; acc[1][1] += a.y * w.y;
            acc[1][2] += a.y * w.z; acc[1][3] += a.y * w.w;
            acc[2][0] += a.z * w.x; acc[2][1] += a.z * w.y;
            acc[2][2] += a.z * w.z; acc[2][3] += a.z * w.w;
            acc[3][0] += a.w * w.x; acc[3][1] += a.w * w.y;
            acc[3][2] += a.w * w.z; acc[3][3] += a.w * w.w;
        }
        __syncthreads();
    }

    int cbase = tx * 4;
    #pragma unroll
    for (int i = 0; i < 4; i++) {
        int r = rbase + ty * 4 + i;
        if (r >= N_NODES) continue;
        float4 o = make_float4(acc[i][0], acc[i][1], acc[i][2], acc[i][3]);
        if (COMBINE) {
            float rd = 1.f / fmaxf(g_deg[r], 1.f);
            float4 ag = *(const float4*)&g_agg[r * 64 + cbase];
            float4 bb = *(const float4*)(bias + cbase);
            o.x = fmaxf(fmaf(ag.x, rd, o.x) + bb.x, 0.f);
            o.y = fmaxf(fmaf(ag.y, rd, o.y) + bb.y, 0.f);
            o.z = fmaxf(fmaf(ag.z, rd, o.z) + bb.z, 0.f);
            o.w = fmaxf(fmaf(ag.w, rd, o.w) + bb.w, 0.f);
        }
        *(float4*)(C + (size_t)r * 64 + cbase) = o;
    }
}

// ---------------- launch -----------------------------------------------------
extern "C" void kernel_launch(void* const* d_in, const int* in_sizes, int n_in,
                              void* d_out, int out_size) {
    const float* x   = (const float*)d_in[0];
    const int*   ei  = (const int*)d_in[1];
    const float* w1l = (const float*)d_in[2];
    const float* w1r = (const float*)d_in[3];
    const float* b1  = (const float*)d_in[4];
    const float* w2l = (const float*)d_in[5];
    const float* w2r = (const float*)d_in[6];
    const float* b2  = (const float*)d_in[7];
    const int* src = ei;             // edge_index[0, :]
    const int* dst = ei + N_EDGES;   // edge_index[1, :]
    float* out = (float*)d_out;

    const int gemm_grid = (N_NODES + 63) / 64;                 // 782
    const int scat_grid = (N_EDGES * 16 + 255) / 256;          // 50000
    const int deg_grid  = (N_EDGES + 255) / 256;

    // layer 1
    zero_kernel<<<2048, 256>>>(1);
    deg_kernel<<<deg_grid, 256>>>(dst);
    gemm64<IN_CH, false, 0, 0><<<gemm_grid, 256>>>(x, w1l, nullptr, nullptr);   // g_y = x@w1_l
    scatter_kernel<<<scat_grid, 256>>>(src, dst);                               // agg += y[src]
    gemm64<IN_CH, true, 0, 1><<<gemm_grid, 256>>>(x, w1r, b1, nullptr);         // g_h = relu(x@w1_r + agg/deg + b1)

    // layer 2
    zero_kernel<<<2048, 256>>>(0);
    gemm64<HID, false, 1, 0><<<gemm_grid, 256>>>(nullptr, w2l, nullptr, nullptr); // g_y = h@w2_l
    scatter_kernel<<<scat_grid, 256>>>(src, dst);
    gemm64<HID, true, 1, 2><<<gemm_grid, 256>>>(nullptr, w2r, b2, out);           // out = relu(h@w2_r + agg/deg + b2)
}

// round 6
// speedup vs baseline: 1.2491x; 1.2491x over previous
#include <cuda_runtime.h>

#define N_NODES 50000
#define N_EDGES 800000
#define IN_CH 128
#define HID 64

#define SB 512
#define NSB ((N_NODES + SB - 1) / SB)   // 98

// ---------------- scratch (static device globals: allocation-free) ----------
__device__ int   g_deg[N_NODES];
__device__ int   g_off[N_NODES];
__device__ int   g_woff[N_NODES];
__device__ int   g_part[NSB];
__device__ int   g_csr[N_EDGES];
__device__ float g_y2[N_NODES * 128];   // [N][128]: cols 0:64 = A@Wl, 64:128 = A@Wr
__device__ float g_h[N_NODES * 64];

// ---------------- f32x2 helpers ---------------------------------------------
__device__ __forceinline__ void fma2(unsigned long long& d,
                                     unsigned long long a,
                                     unsigned long long b) {
    asm("fma.rn.f32x2 %0, %1, %2, %0;" : "+l"(d) : "l"(a), "l"(b));
}
__device__ __forceinline__ float2 u2f(unsigned long long v) {
    float2 r;
    asm("mov.b64 {%0, %1}, %2;" : "=f"(r.x), "=f"(r.y) : "l"(v));
    return r;
}

// ---------------- CSR build --------------------------------------------------
__global__ void zero_deg_kernel() {
    int i = blockIdx.x * blockDim.x + threadIdx.x;
    if (i < N_NODES) g_deg[i] = 0;
}

__global__ void hist_kernel(const int* __restrict__ dst) {
    int e = blockIdx.x * blockDim.x + threadIdx.x;
    if (e < N_EDGES) atomicAdd(&g_deg[dst[e]], 1);
}

__global__ void scan1_kernel() {   // grid NSB, block SB: per-block exclusive scan
    __shared__ int s[SB];
    int t = threadIdx.x;
    int i = blockIdx.x * SB + t;
    int v = (i < N_NODES) ? g_deg[i] : 0;
    s[t] = v;
    __syncthreads();
    #pragma unroll
    for (int d = 1; d < SB; d <<= 1) {
        int add = (t >= d) ? s[t - d] : 0;
        __syncthreads();
        s[t] += add;
        __syncthreads();
    }
    if (i < N_NODES) g_off[i] = s[t] - v;          // exclusive within block
    if (t == SB - 1) g_part[blockIdx.x] = s[t];    // block total
}

__global__ void scan2_kernel() {   // 1 block, 128 threads: scan block totals
    __shared__ int s[128];
    int t = threadIdx.x;
    int v = (t < NSB) ? g_part[t] : 0;
    s[t] = v;
    __syncthreads();
    #pragma unroll
    for (int d = 1; d < 128; d <<= 1) {
        int add = (t >= d) ? s[t - d] : 0;
        __syncthreads();
        s[t] += add;
        __syncthreads();
    }
    if (t < NSB) g_part[t] = s[t] - v;             // exclusive
}

__global__ void scan3_kernel() {
    int i = blockIdx.x * SB + threadIdx.x;
    if (i < N_NODES) {
        int o = g_off[i] + g_part[blockIdx.x];
        g_off[i] = o;
        g_woff[i] = o;
    }
}

__global__ void fill_kernel(const int* __restrict__ src,
                            const int* __restrict__ dst) {
    int e = blockIdx.x * blockDim.x + threadIdx.x;
    if (e < N_EDGES) {
        int pos = atomicAdd(&g_woff[dst[e]], 1);
        g_csr[pos] = src[e];
    }
}

// ---------------- merged GEMM: g_y2[N,128] = A[N,K] @ [Wl | Wr] -------------
// 256 threads, 64 rows/block, per-thread 4 rows x 8 cols as 4x4 f32x2 accs.
// Ws[64][128]: k-chunk x (128 cols). Asd[16][136]: k-subchunk x duplicated
// rows: Asd[k][2r] == Asd[k][2r+1] == A[r][k]  -> LDS.128 yields (a,a) pairs
// directly, zero pack cost for fma.rn.f32x2.
// NOTE (R5 bugfix): compute must read Ws[ks + k], not Ws[k] — Ws holds the
// full 64-row k-chunk while Asd holds only the current 16-row sub-chunk.
template<int K, int ASEL>
__global__ void __launch_bounds__(256) gemm2_kernel(const float* __restrict__ Aext,
                                                    const float* __restrict__ Wl,
                                                    const float* __restrict__ Wr) {
    const float* A = (ASEL == 1) ? (const float*)g_h : Aext;

    __shared__ float Ws[64][128];
    __shared__ float Asd[16][136];

    int tid = threadIdx.x;
    int tx = tid & 15;        // col group
    int ty = tid >> 4;        // row group
    int rbase = blockIdx.x * 64;

    unsigned long long acc[4][4] = {};

    int ar = tid >> 2;        // Asd stage: row 0..63
    int ak4 = (tid & 3) << 2; // Asd stage: k offset 0,4,8,12

    for (int kc = 0; kc < K; kc += 64) {
        for (int ks = 0; ks < 64; ks += 16) {
            if (ks == 0) {
                // stage Ws[64][128] for this kc: 2048 float4 = 8 per thread
                #pragma unroll
                for (int i = 0; i < 8; i++) {
                    int li = tid + i * 256;
                    int wk = li >> 5;
                    int wc4 = (li & 31) << 2;
                    const float* srcp = (wc4 < 64)
                        ? (Wl + (size_t)(kc + wk) * 64 + wc4)
                        : (Wr + (size_t)(kc + wk) * 64 + (wc4 - 64));
                    *(float4*)&Ws[wk][wc4] = *(const float4*)srcp;
                }
            }
            // stage Asd[16][dup 128] : one float4 per thread
            {
                int gr = rbase + ar;
                float4 a = make_float4(0.f, 0.f, 0.f, 0.f);
                if (gr < N_NODES)
                    a = *(const float4*)(A + (size_t)gr * K + kc + ks + ak4);
                *(float2*)&Asd[ak4 + 0][2 * ar] = make_float2(a.x, a.x);
                *(float2*)&Asd[ak4 + 1][2 * ar] = make_float2(a.y, a.y);
                *(float2*)&Asd[ak4 + 2][2 * ar] = make_float2(a.z, a.z);
                *(float2*)&Asd[ak4 + 3][2 * ar] = make_float2(a.w, a.w);
            }
            __syncthreads();

            #pragma unroll
            for (int k = 0; k < 16; k++) {
                ulonglong2 a01 = *(const ulonglong2*)&Asd[k][ty * 8];
                ulonglong2 a23 = *(const ulonglong2*)&Asd[k][ty * 8 + 4];
                ulonglong2 w01 = *(const ulonglong2*)&Ws[ks + k][tx * 4];       // <- fixed
                ulonglong2 w23 = *(const ulonglong2*)&Ws[ks + k][64 + tx * 4];  // <- fixed
                fma2(acc[0][0], a01.x, w01.x); fma2(acc[0][1], a01.x, w01.y);
                fma2(acc[0][2], a01.x, w23.x); fma2(acc[0][3], a01.x, w23.y);
                fma2(acc[1][0], a01.y, w01.x); fma2(acc[1][1], a01.y, w01.y);
                fma2(acc[1][2], a01.y, w23.x); fma2(acc[1][3], a01.y, w23.y);
                fma2(acc[2][0], a23.x, w01.x); fma2(acc[2][1], a23.x, w01.y);
                fma2(acc[2][2], a23.x, w23.x); fma2(acc[2][3], a23.x, w23.y);
                fma2(acc[3][0], a23.y, w01.x); fma2(acc[3][1], a23.y, w01.y);
                fma2(acc[3][2], a23.y, w23.x); fma2(acc[3][3], a23.y, w23.y);
            }
            __syncthreads();
        }
    }

    #pragma unroll
    for (int i = 0; i < 4; i++) {
        int r = rbase + ty * 4 + i;
        if (r >= N_NODES) continue;
        float2 p0 = u2f(acc[i][0]);
        float2 p1 = u2f(acc[i][1]);
        float2 p2 = u2f(acc[i][2]);
        float2 p3 = u2f(acc[i][3]);
        *(float4*)(g_y2 + (size_t)r * 128 + tx * 4) =
            make_float4(p0.x, p0.y, p1.x, p1.y);
        *(float4*)(g_y2 + (size_t)r * 128 + 64 + tx * 4) =
            make_float4(p2.x, p2.y, p3.x, p3.y);
    }
}

// ---------------- gather + combine ------------------------------------------
// one warp per destination node; acc = sum_{s in nbr} y2[s][0:64];
// out[n] = relu(acc/deg + y2[n][64:128] + b)
__global__ void __launch_bounds__(256) gather_kernel(const float* __restrict__ bias,
                                                     float* __restrict__ outp) {
    int gw = (blockIdx.x * blockDim.x + threadIdx.x) >> 5;
    int lane = threadIdx.x & 31;
    if (gw >= N_NODES) return;

    int off = g_off[gw];
    int deg = g_deg[gw];

    float2 acc0 = make_float2(0.f, 0.f);
    float2 acc1 = make_float2(0.f, 0.f);
    const unsigned FULL = 0xffffffffu;

    for (int base = 0; base < deg; base += 32) {
        int n = min(32, deg - base);
        int sv = (lane < n) ? __ldg(&g_csr[off + base + lane]) : 0;
        int k = 0;
        for (; k + 4 <= n; k += 4) {
            int s0 = __shfl_sync(FULL, sv, k);
            int s1 = __shfl_sync(FULL, sv, k + 1);
            int s2 = __shfl_sync(FULL, sv, k + 2);
            int s3 = __shfl_sync(FULL, sv, k + 3);
            float2 v0 = *(const float2*)(g_y2 + (size_t)s0 * 128 + lane * 2);
            float2 v1 = *(const float2*)(g_y2 + (size_t)s1 * 128 + lane * 2);
            float2 v2 = *(const float2*)(g_y2 + (size_t)s2 * 128 + lane * 2);
            float2 v3 = *(const float2*)(g_y2 + (size_t)s3 * 128 + lane * 2);
            acc0.x += v0.x; acc0.y += v0.y;
            acc1.x += v1.x; acc1.y += v1.y;
            acc0.x += v2.x; acc0.y += v2.y;
            acc1.x += v3.x; acc1.y += v3.y;
        }
        for (; k < n; k++) {
            int s0 = __shfl_sync(FULL, sv, k);
            float2 v = *(const float2*)(g_y2 + (size_t)s0 * 128 + lane * 2);
            acc0.x += v.x; acc0.y += v.y;
        }
    }

    float scale = 1.f / fmaxf((float)deg, 1.f);
    float2 z = *(const float2*)(g_y2 + (size_t)gw * 128 + 64 + lane * 2);
    float2 b = *(const float2*)(bias + lane * 2);
    float2 o;
    o.x = fmaxf(fmaf(acc0.x + acc1.x, scale, z.x) + b.x, 0.f);
    o.y = fmaxf(fmaf(acc0.y + acc1.y, scale, z.y) + b.y, 0.f);
    *(float2*)(outp + (size_t)gw * 64 + lane * 2) = o;
}

// ---------------- launch -----------------------------------------------------
extern "C" void kernel_launch(void* const* d_in, const int* in_sizes, int n_in,
                              void* d_out, int out_size) {
    const float* x   = (const float*)d_in[0];
    const int*   ei  = (const int*)d_in[1];
    const float* w1l = (const float*)d_in[2];
    const float* w1r = (const float*)d_in[3];
    const float* b1  = (const float*)d_in[4];
    const float* w2l = (const float*)d_in[5];
    const float* w2r = (const float*)d_in[6];
    const float* b2  = (const float*)d_in[7];
    const int* src = ei;             // edge_index[0, :]
    const int* dst = ei + N_EDGES;   // edge_index[1, :]
    float* out = (float*)d_out;

    float* h_ptr = nullptr;
    cudaGetSymbolAddress((void**)&h_ptr, g_h);

    const int gemm_grid   = (N_NODES + 63) / 64;            // 782
    const int gather_grid = (N_NODES * 32 + 255) / 256;     // 6250
    const int edge_grid   = (N_EDGES + 255) / 256;

    // ---- CSR build (once, reused by both layers) ----
    zero_deg_kernel<<<NSB, SB>>>();
    hist_kernel<<<edge_grid, 256>>>(dst);
    scan1_kernel<<<NSB, SB>>>();
    scan2_kernel<<<1, 128>>>();
    scan3_kernel<<<NSB, SB>>>();
    fill_kernel<<<edge_grid, 256>>>(src, dst);

    // ---- layer 1 ----
    gemm2_kernel<IN_CH, 0><<<gemm_grid, 256>>>(x, w1l, w1r);   // g_y2 = x@[w1l|w1r]
    gather_kernel<<<gather_grid, 256>>>(b1, h_ptr);            // g_h = relu(...)

    // ---- layer 2 ----
    gemm2_kernel<HID, 1><<<gemm_grid, 256>>>(nullptr, w2l, w2r); // g_y2 = h@[w2l|w2r]
    gather_kernel<<<gather_grid, 256>>>(b2, out);                // out = relu(...)
}

// round 7
// speedup vs baseline: 1.3953x; 1.1170x over previous
#include <cuda_runtime.h>

#define N_NODES 50000
#define N_EDGES 800000
#define IN_CH 128
#define HID 64

#define SB 512
#define NSB ((N_NODES + SB - 1) / SB)   // 98

// ---------------- scratch (static device globals: allocation-free) ----------
__device__ int   g_deg[N_NODES];
__device__ int   g_off[N_NODES];
__device__ int   g_woff[N_NODES];
__device__ int   g_part[NSB];
__device__ int   g_csr[N_EDGES];
__device__ float g_y2[N_NODES * 128];   // [N][128]: cols 0:64 = A@Wl, 64:128 = A@Wr
__device__ float g_h[N_NODES * 64];

// ---------------- f32x2 helpers ---------------------------------------------
__device__ __forceinline__ void fma2(unsigned long long& d,
                                     unsigned long long a,
                                     unsigned long long b) {
    asm("fma.rn.f32x2 %0, %1, %2, %0;" : "+l"(d) : "l"(a), "l"(b));
}
__device__ __forceinline__ float2 u2f(unsigned long long v) {
    float2 r;
    asm("mov.b64 {%0, %1}, %2;" : "=f"(r.x), "=f"(r.y) : "l"(v));
    return r;
}

// ---------------- CSR build --------------------------------------------------
__global__ void zero_deg_kernel() {
    int i = blockIdx.x * blockDim.x + threadIdx.x;
    if (i < N_NODES) g_deg[i] = 0;
}

__global__ void hist_kernel(const int* __restrict__ dst) {
    int e = blockIdx.x * blockDim.x + threadIdx.x;
    if (e < N_EDGES) atomicAdd(&g_deg[dst[e]], 1);
}

__global__ void scan1_kernel() {   // grid NSB, block SB: per-block exclusive scan
    __shared__ int s[SB];
    int t = threadIdx.x;
    int i = blockIdx.x * SB + t;
    int v = (i < N_NODES) ? g_deg[i] : 0;
    s[t] = v;
    __syncthreads();
    #pragma unroll
    for (int d = 1; d < SB; d <<= 1) {
        int add = (t >= d) ? s[t - d] : 0;
        __syncthreads();
        s[t] += add;
        __syncthreads();
    }
    if (i < N_NODES) g_off[i] = s[t] - v;          // exclusive within block
    if (t == SB - 1) g_part[blockIdx.x] = s[t];    // block total
}

__global__ void scan2_kernel() {   // 1 block, 128 threads: scan block totals
    __shared__ int s[128];
    int t = threadIdx.x;
    int v = (t < NSB) ? g_part[t] : 0;
    s[t] = v;
    __syncthreads();
    #pragma unroll
    for (int d = 1; d < 128; d <<= 1) {
        int add = (t >= d) ? s[t - d] : 0;
        __syncthreads();
        s[t] += add;
        __syncthreads();
    }
    if (t < NSB) g_part[t] = s[t] - v;             // exclusive
}

__global__ void scan3_kernel() {
    int i = blockIdx.x * SB + threadIdx.x;
    if (i < N_NODES) {
        int o = g_off[i] + g_part[blockIdx.x];
        g_off[i] = o;
        g_woff[i] = o;
    }
}

__global__ void fill_kernel(const int* __restrict__ src,
                            const int* __restrict__ dst) {
    int e = blockIdx.x * blockDim.x + threadIdx.x;
    if (e < N_EDGES) {
        int pos = atomicAdd(&g_woff[dst[e]], 1);
        g_csr[pos] = src[e];
    }
}

// ---------------- merged GEMM: g_y2[N,128] = A[N,K] @ [Wl | Wr] -------------
// 256 threads, 64 rows/block, per-thread 4 rows x 8 cols as 4x4 f32x2 accs.
// Ws[64][128]: k-chunk x (128 cols). Asd[16][136]: k-subchunk x duplicated
// rows: Asd[k][2r] == Asd[k][2r+1] == A[r][k]  -> LDS.128 yields (a,a) pairs
// directly, zero pack cost for fma.rn.f32x2.
template<int K, int ASEL>
__global__ void __launch_bounds__(256) gemm2_kernel(const float* __restrict__ Aext,
                                                    const float* __restrict__ Wl,
                                                    const float* __restrict__ Wr) {
    const float* A = (ASEL == 1) ? (const float*)g_h : Aext;

    __shared__ float Ws[64][128];
    __shared__ float Asd[16][136];

    int tid = threadIdx.x;
    int tx = tid & 15;        // col group
    int ty = tid >> 4;        // row group
    int rbase = blockIdx.x * 64;

    unsigned long long acc[4][4] = {};

    int ar = tid >> 2;        // Asd stage: row 0..63
    int ak4 = (tid & 3) << 2; // Asd stage: k offset 0,4,8,12

    for (int kc = 0; kc < K; kc += 64) {
        for (int ks = 0; ks < 64; ks += 16) {
            if (ks == 0) {
                // stage Ws[64][128] for this kc: 2048 float4 = 8 per thread
                #pragma unroll
                for (int i = 0; i < 8; i++) {
                    int li = tid + i * 256;
                    int wk = li >> 5;
                    int wc4 = (li & 31) << 2;
                    const float* srcp = (wc4 < 64)
                        ? (Wl + (size_t)(kc + wk) * 64 + wc4)
                        : (Wr + (size_t)(kc + wk) * 64 + (wc4 - 64));
                    *(float4*)&Ws[wk][wc4] = *(const float4*)srcp;
                }
            }
            // stage Asd[16][dup 128] : one float4 per thread
            {
                int gr = rbase + ar;
                float4 a = make_float4(0.f, 0.f, 0.f, 0.f);
                if (gr < N_NODES)
                    a = *(const float4*)(A + (size_t)gr * K + kc + ks + ak4);
                *(float2*)&Asd[ak4 + 0][2 * ar] = make_float2(a.x, a.x);
                *(float2*)&Asd[ak4 + 1][2 * ar] = make_float2(a.y, a.y);
                *(float2*)&Asd[ak4 + 2][2 * ar] = make_float2(a.z, a.z);
                *(float2*)&Asd[ak4 + 3][2 * ar] = make_float2(a.w, a.w);
            }
            __syncthreads();

            #pragma unroll
            for (int k = 0; k < 16; k++) {
                ulonglong2 a01 = *(const ulonglong2*)&Asd[k][ty * 8];
                ulonglong2 a23 = *(const ulonglong2*)&Asd[k][ty * 8 + 4];
                ulonglong2 w01 = *(const ulonglong2*)&Ws[ks + k][tx * 4];
                ulonglong2 w23 = *(const ulonglong2*)&Ws[ks + k][64 + tx * 4];
                fma2(acc[0][0], a01.x, w01.x); fma2(acc[0][1], a01.x, w01.y);
                fma2(acc[0][2], a01.x, w23.x); fma2(acc[0][3], a01.x, w23.y);
                fma2(acc[1][0], a01.y, w01.x); fma2(acc[1][1], a01.y, w01.y);
                fma2(acc[1][2], a01.y, w23.x); fma2(acc[1][3], a01.y, w23.y);
                fma2(acc[2][0], a23.x, w01.x); fma2(acc[2][1], a23.x, w01.y);
                fma2(acc[2][2], a23.x, w23.x); fma2(acc[2][3], a23.x, w23.y);
                fma2(acc[3][0], a23.y, w01.x); fma2(acc[3][1], a23.y, w01.y);
                fma2(acc[3][2], a23.y, w23.x); fma2(acc[3][3], a23.y, w23.y);
            }
            __syncthreads();
        }
    }

    #pragma unroll
    for (int i = 0; i < 4; i++) {
        int r = rbase + ty * 4 + i;
        if (r >= N_NODES) continue;
        float2 p0 = u2f(acc[i][0]);
        float2 p1 = u2f(acc[i][1]);
        float2 p2 = u2f(acc[i][2]);
        float2 p3 = u2f(acc[i][3]);
        *(float4*)(g_y2 + (size_t)r * 128 + tx * 4) =
            make_float4(p0.x, p0.y, p1.x, p1.y);
        *(float4*)(g_y2 + (size_t)r * 128 + 64 + tx * 4) =
            make_float4(p2.x, p2.y, p3.x, p3.y);
    }
}

// ---------------- gather + combine ------------------------------------------
// One warp per destination node. Half-warp per edge: lanes 0-15 take edge k,
// lanes 16-31 take edge k+1; each lane loads float4 of columns (lane&15)*4.
// Cross-half shfl reduction at the end; lanes 0-15 write the output.
__global__ void __launch_bounds__(256) gather_kernel(const float* __restrict__ bias,
                                                     float* __restrict__ outp) {
    int gw = (blockIdx.x * blockDim.x + threadIdx.x) >> 5;
    int lane = threadIdx.x & 31;
    if (gw >= N_NODES) return;

    int off = g_off[gw];
    int deg = g_deg[gw];
    int half = lane >> 4;
    int c4 = (lane & 15) << 2;
    const unsigned FULL = 0xffffffffu;

    float4 acc0 = make_float4(0.f, 0.f, 0.f, 0.f);
    float4 acc1 = make_float4(0.f, 0.f, 0.f, 0.f);

    for (int base = 0; base < deg; base += 32) {
        int n = min(32, deg - base);
        int sv = (lane < n) ? __ldg(&g_csr[off + base + lane]) : 0;
        int k = 0;
        for (; k + 4 <= n; k += 4) {
            int sa = __shfl_sync(FULL, sv, k + half);
            int sb = __shfl_sync(FULL, sv, k + 2 + half);
            float4 va = *(const float4*)(g_y2 + (size_t)sa * 128 + c4);
            float4 vb = *(const float4*)(g_y2 + (size_t)sb * 128 + c4);
            acc0.x += va.x; acc0.y += va.y; acc0.z += va.z; acc0.w += va.w;
            acc1.x += vb.x; acc1.y += vb.y; acc1.z += vb.z; acc1.w += vb.w;
        }
        if (k + 2 <= n) {
            int sa = __shfl_sync(FULL, sv, k + half);
            float4 va = *(const float4*)(g_y2 + (size_t)sa * 128 + c4);
            acc0.x += va.x; acc0.y += va.y; acc0.z += va.z; acc0.w += va.w;
            k += 2;
        }
        if (k < n) {   // one leftover edge: lanes 0-15 only
            int sa = __shfl_sync(FULL, sv, k);
            if (half == 0) {
                float4 va = *(const float4*)(g_y2 + (size_t)sa * 128 + c4);
                acc0.x += va.x; acc0.y += va.y; acc0.z += va.z; acc0.w += va.w;
            }
        }
    }

    float4 acc;
    acc.x = acc0.x + acc1.x;
    acc.y = acc0.y + acc1.y;
    acc.z = acc0.z + acc1.z;
    acc.w = acc0.w + acc1.w;
    acc.x += __shfl_down_sync(FULL, acc.x, 16);
    acc.y += __shfl_down_sync(FULL, acc.y, 16);
    acc.z += __shfl_down_sync(FULL, acc.z, 16);
    acc.w += __shfl_down_sync(FULL, acc.w, 16);

    if (half == 0) {
        float scale = 1.f / fmaxf((float)deg, 1.f);
        float4 z = *(const float4*)(g_y2 + (size_t)gw * 128 + 64 + c4);
        float4 b = *(const float4*)(bias + c4);
        float4 o;
        o.x = fmaxf(fmaf(acc.x, scale, z.x) + b.x, 0.f);
        o.y = fmaxf(fmaf(acc.y, scale, z.y) + b.y, 0.f);
        o.z = fmaxf(fmaf(acc.z, scale, z.z) + b.z, 0.f);
        o.w = fmaxf(fmaf(acc.w, scale, z.w) + b.w, 0.f);
        *(float4*)(outp + (size_t)gw * 64 + c4) = o;
    }
}

// ---------------- launch -----------------------------------------------------
extern "C" void kernel_launch(void* const* d_in, const int* in_sizes, int n_in,
                              void* d_out, int out_size) {
    const float* x   = (const float*)d_in[0];
    const int*   ei  = (const int*)d_in[1];
    const float* w1l = (const float*)d_in[2];
    const float* w1r = (const float*)d_in[3];
    const float* b1  = (const float*)d_in[4];
    const float* w2l = (const float*)d_in[5];
    const float* w2r = (const float*)d_in[6];
    const float* b2  = (const float*)d_in[7];
    const int* src = ei;             // edge_index[0, :]
    const int* dst = ei + N_EDGES;   // edge_index[1, :]
    float* out = (float*)d_out;

    float* h_ptr = nullptr;
    cudaGetSymbolAddress((void**)&h_ptr, g_h);

    // lazily-created side stream + fork/join events (resource init only;
    // the launched work is identical on every call)
    static cudaStream_t s2 = nullptr;
    static cudaEvent_t e_fork = nullptr, e_join = nullptr;
    if (!s2) {
        cudaStreamCreateWithFlags(&s2, cudaStreamNonBlocking);
        cudaEventCreateWithFlags(&e_fork, cudaEventDisableTiming);
        cudaEventCreateWithFlags(&e_join, cudaEventDisableTiming);
    }

    const int gemm_grid   = (N_NODES + 63) / 64;            // 782
    const int gather_grid = (N_NODES * 32 + 255) / 256;     // 6250
    const int edge_grid   = (N_EDGES + 255) / 256;

    // ---- fork: CSR build on s2, concurrent with gemm1 on main stream ----
    cudaEventRecord(e_fork, 0);
    cudaStreamWaitEvent(s2, e_fork, 0);

    zero_deg_kernel<<<NSB, SB, 0, s2>>>();
    hist_kernel<<<edge_grid, 256, 0, s2>>>(dst);
    scan1_kernel<<<NSB, SB, 0, s2>>>();
    scan2_kernel<<<1, 128, 0, s2>>>();
    scan3_kernel<<<NSB, SB, 0, s2>>>();
    fill_kernel<<<edge_grid, 256, 0, s2>>>(src, dst);
    cudaEventRecord(e_join, s2);

    // main stream: layer-1 GEMM runs concurrently with CSR build
    gemm2_kernel<IN_CH, 0><<<gemm_grid, 256>>>(x, w1l, w1r);   // g_y2 = x@[w1l|w1r]

    // ---- join: gather needs both CSR and g_y2 ----
    cudaStreamWaitEvent(0, e_join, 0);
    gather_kernel<<<gather_grid, 256>>>(b1, h_ptr);            // g_h = relu(...)

    // ---- layer 2 ----
    gemm2_kernel<HID, 1><<<gemm_grid, 256>>>(nullptr, w2l, w2r); // g_y2 = h@[w2l|w2r]
    gather_kernel<<<gather_grid, 256>>>(b2, out);                // out = relu(...)
}